// round 5
// baseline (speedup 1.0000x reference)
#include <cuda_runtime.h>
#include <cuda_bf16.h>
#include <math.h>

// Problem constants
#define BATCH 2
#define NPTS  8192
#define CDIM  256
#define KNB   15
// tau = 0.2 -> 1/tau = 5.0 (exact in fp32), applied AFTER top-k selection.

// ---------------------------------------------------------------------------
// Static device scratch (allocation-free rule: __device__ globals only)
// ---------------------------------------------------------------------------
__device__ float g_fx[(size_t)BATCH * NPTS * CDIM];   // L2-normalized feat_x
__device__ float g_fy[(size_t)BATCH * NPTS * CDIM];   // L2-normalized feat_y
__device__ float g_sim[(size_t)BATCH * NPTS * NPTS];  // 512 MB sim (UNscaled)

// ---------------------------------------------------------------------------
// Kernel 1: L2-normalize rows of both feature tensors.
//   blockIdx.x in [0, 2*BATCH*NPTS): first half -> feat_x, second -> feat_y.
//   One block (256 threads) per row, C = 256. Stores v / max(norm,1e-12)
//   with a true division to match the reference's rounding.
// ---------------------------------------------------------------------------
__global__ __launch_bounds__(CDIM) void norm_kernel(const float* __restrict__ x,
                                                    const float* __restrict__ y)
{
    int row = blockIdx.x;
    const int total = BATCH * NPTS;
    const float* src;
    float* dst;
    if (row < total) {
        src = x + (size_t)row * CDIM;
        dst = g_fx + (size_t)row * CDIM;
    } else {
        row -= total;
        src = y + (size_t)row * CDIM;
        dst = g_fy + (size_t)row * CDIM;
    }

    float v = src[threadIdx.x];
    float s = v * v;

    __shared__ float red[8];
    #pragma unroll
    for (int o = 16; o; o >>= 1) s += __shfl_xor_sync(0xffffffffu, s, o);
    if ((threadIdx.x & 31) == 0) red[threadIdx.x >> 5] = s;
    __syncthreads();
    if (threadIdx.x < 8) {
        float t = red[threadIdx.x];
        #pragma unroll
        for (int o = 4; o; o >>= 1) t += __shfl_xor_sync(0xffu, t, o);
        if (threadIdx.x == 0) red[0] = t;
    }
    __syncthreads();

    float norm = fmaxf(sqrtf(red[0]), 1e-12f);
    dst[threadIdx.x] = v / norm;   // true division, matches reference
}

// ---------------------------------------------------------------------------
// Kernel 2: fp32 NT-GEMM  sim[b] = fx[b] (NPTS x C) * fy[b]^T (C x NPTS)
//   128x128 block tile, BK=16, 8x8 micro-tile, 256 threads.
//   __launch_bounds__(256, 2): 2 CTAs/SM so one CTA's barrier/LDG shadow is
//   filled by the other's FFMAs. Register-staged double buffering.
//   Load mapping: r = tid&127 -> all 32 lanes of a warp hold distinct
//   consecutive rows, so the scalar transpose stores As[k][r] are
//   conflict-free (32 distinct banks).
// ---------------------------------------------------------------------------
#define BM 128
#define BN 128
#define BK 16
#define TM 8
#define TN 8

__global__ __launch_bounds__(256, 2) void sgemm_nt_kernel()
{
    const int b = blockIdx.z;
    const float* __restrict__ A  = g_fx + (size_t)b * NPTS * CDIM;
    const float* __restrict__ Bm = g_fy + (size_t)b * NPTS * CDIM;
    float* __restrict__ Cm = g_sim + (size_t)b * NPTS * NPTS;

    const int rowBase = blockIdx.y * BM;   // x rows
    const int colBase = blockIdx.x * BN;   // y cols

    __shared__ float As[BK][BM];           // 8 KB
    __shared__ float Bs[BK][BN];           // 8 KB

    const int tid = threadIdx.x;
    const int tx = tid & 15;     // 0..15 -> col group
    const int ty = tid >> 4;     // 0..15 -> row group

    const int r   = tid & 127;            // row within tile
    const int kq0 = (tid >> 7) << 3;      // 0 or 8

    const float* pa = A  + (size_t)(rowBase + r) * CDIM + kq0;
    const float* pb = Bm + (size_t)(colBase + r) * CDIM + kq0;

    float acc[TM][TN];
    #pragma unroll
    for (int i = 0; i < TM; i++)
        #pragma unroll
        for (int j = 0; j < TN; j++) acc[i][j] = 0.0f;

    // Prefetch first k-tile into registers (4 independent LDG.128).
    float4 va0 = *(const float4*)(pa);
    float4 va1 = *(const float4*)(pa + 4);
    float4 vb0 = *(const float4*)(pb);
    float4 vb1 = *(const float4*)(pb + 4);

    for (int k0 = 0; k0 < CDIM; k0 += BK) {
        As[kq0 + 0][r] = va0.x; As[kq0 + 1][r] = va0.y;
        As[kq0 + 2][r] = va0.z; As[kq0 + 3][r] = va0.w;
        As[kq0 + 4][r] = va1.x; As[kq0 + 5][r] = va1.y;
        As[kq0 + 6][r] = va1.z; As[kq0 + 7][r] = va1.w;
        Bs[kq0 + 0][r] = vb0.x; Bs[kq0 + 1][r] = vb0.y;
        Bs[kq0 + 2][r] = vb0.z; Bs[kq0 + 3][r] = vb0.w;
        Bs[kq0 + 4][r] = vb1.x; Bs[kq0 + 5][r] = vb1.y;
        Bs[kq0 + 6][r] = vb1.z; Bs[kq0 + 7][r] = vb1.w;
        __syncthreads();

        if (k0 + BK < CDIM) {
            int nk = k0 + BK;
            va0 = *(const float4*)(pa + nk);
            va1 = *(const float4*)(pa + nk + 4);
            vb0 = *(const float4*)(pb + nk);
            vb1 = *(const float4*)(pb + nk + 4);
        }

        #pragma unroll
        for (int kk = 0; kk < BK; kk++) {
            float ra[TM], rb[TN];
            float4 a0 = *(const float4*)&As[kk][ty * TM];
            float4 a1 = *(const float4*)&As[kk][ty * TM + 4];
            ra[0] = a0.x; ra[1] = a0.y; ra[2] = a0.z; ra[3] = a0.w;
            ra[4] = a1.x; ra[5] = a1.y; ra[6] = a1.z; ra[7] = a1.w;
            float4 b0 = *(const float4*)&Bs[kk][tx * TN];
            float4 b1 = *(const float4*)&Bs[kk][tx * TN + 4];
            rb[0] = b0.x; rb[1] = b0.y; rb[2] = b0.z; rb[3] = b0.w;
            rb[4] = b1.x; rb[5] = b1.y; rb[6] = b1.z; rb[7] = b1.w;

            #pragma unroll
            for (int i = 0; i < TM; i++)
                #pragma unroll
                for (int j = 0; j < TN; j++)
                    acc[i][j] = fmaf(ra[i], rb[j], acc[i][j]);
        }
        __syncthreads();
    }

    #pragma unroll
    for (int i = 0; i < TM; i++) {
        size_t off = (size_t)(rowBase + ty * TM + i) * NPTS + colBase + tx * TN;
        *(float4*)(Cm + off)     = make_float4(acc[i][0], acc[i][1], acc[i][2], acc[i][3]);
        *(float4*)(Cm + off + 4) = make_float4(acc[i][4], acc[i][5], acc[i][6], acc[i][7]);
    }
}

// ---------------------------------------------------------------------------
// Kernel 3: per-row top-15 + softmax. Exact jax.lax.top_k semantics
//   (descending values, lowest index on ties). Runs on UNSCALED sim
//   (monotone in sim/tau -> identical selection); 1/tau = 5.0 applied to the
//   15 winners before softmax.
//
//   Phase 1: each of 256 threads reads its 32 row elements once (coalesced
//            float4) and keeps an exact register-resident sorted top-15.
//            (top-15 of the union == top-15 of the per-thread top-15s)
//   Phase 2: per-thread lists -> smem; 15 merge rounds. Each round reduces
//            256 candidate heads with a packed 64-bit key:
//              [monotone-float val (32) | 8191-idx (13) | tid (8)]
//            so a single max implements (val desc, idx asc) + winner id.
// ---------------------------------------------------------------------------
__device__ __forceinline__ bool tk_better(float v, int i, float v2, int i2)
{
    return v > v2 || (v == v2 && i < i2);
}

__device__ __forceinline__ void tk_insert(float v, int idx, float lv[KNB], int li[KNB])
{
    if (tk_better(v, idx, lv[KNB - 1], li[KNB - 1])) {
        lv[KNB - 1] = v; li[KNB - 1] = idx;
        #pragma unroll
        for (int k = KNB - 1; k > 0; k--) {
            if (tk_better(lv[k], li[k], lv[k - 1], li[k - 1])) {
                float tv = lv[k]; lv[k] = lv[k - 1]; lv[k - 1] = tv;
                int   ti = li[k]; li[k] = li[k - 1]; li[k - 1] = ti;
            }
        }
    }
}

__device__ __forceinline__ unsigned long long tk_key(float v, int idx, int tid)
{
    unsigned int u = __float_as_uint(v);
    unsigned int s = (u & 0x80000000u) ? ~u : (u | 0x80000000u); // monotone map
    unsigned int low = ((0x1FFFu & ~(unsigned int)idx) << 8) | (unsigned int)tid;
    return ((unsigned long long)s << 32) | low;
}

__global__ __launch_bounds__(256) void topk_kernel(float* __restrict__ out)
{
    const int x = blockIdx.x;
    const int b = blockIdx.y;
    const float4* __restrict__ row4 =
        (const float4*)(g_sim + ((size_t)b * NPTS + x) * NPTS);

    __shared__ float          sval[256 * KNB];     // 15 KB
    __shared__ unsigned short sidx[256 * KNB];     // 7.5 KB
    __shared__ unsigned long long warpKey[8];
    __shared__ unsigned long long finalKey;
    __shared__ float outv[KNB];
    __shared__ int   outi[KNB];

    const int tid  = threadIdx.x;
    const int lane = tid & 31;
    const int wid  = tid >> 5;

    // Phase 1: register top-15 over this thread's 32 elements.
    float lv[KNB]; int li[KNB];
    #pragma unroll
    for (int k = 0; k < KNB; k++) { lv[k] = -INFINITY; li[k] = 0x7fffffff; }

    #pragma unroll
    for (int j = 0; j < 8; j++) {
        float4 v = row4[tid + 256 * j];
        int base = 4 * (tid + 256 * j);
        tk_insert(v.x, base + 0, lv, li);
        tk_insert(v.y, base + 1, lv, li);
        tk_insert(v.z, base + 2, lv, li);
        tk_insert(v.w, base + 3, lv, li);
    }

    #pragma unroll
    for (int k = 0; k < KNB; k++) {
        sval[tid * KNB + k] = lv[k];
        sidx[tid * KNB + k] = (unsigned short)li[k];
    }
    __syncthreads();

    // Phase 2: 15 merge rounds over the 256 list heads.
    int p = 0;
    for (int t = 0; t < KNB; t++) {
        float v  = sval[tid * KNB + p];
        int  idx = sidx[tid * KNB + p];
        unsigned long long key = tk_key(v, idx, tid);

        #pragma unroll
        for (int o = 16; o; o >>= 1) {
            unsigned long long ok = __shfl_xor_sync(0xffffffffu, key, o);
            if (ok > key) key = ok;
        }
        if (lane == 0) warpKey[wid] = key;
        __syncthreads();

        if (tid < 8) {
            unsigned long long k2 = warpKey[tid];
            #pragma unroll
            for (int o = 4; o; o >>= 1) {
                unsigned long long ok = __shfl_xor_sync(0xffu, k2, o);
                if (ok > k2) k2 = ok;
            }
            if (tid == 0) finalKey = k2;
        }
        __syncthreads();

        unsigned long long fk = finalKey;
        if ((int)(fk & 0xffu) == tid) p++;          // winner advances its head
        if (tid == 0) {
            unsigned int s = (unsigned int)(fk >> 32);
            unsigned int u = (s & 0x80000000u) ? (s & 0x7fffffffu) : ~s;
            outv[t] = __uint_as_float(u);
            outi[t] = 0x1FFF - (int)((fk >> 8) & 0x1FFFu);
        }
        __syncthreads();   // protect warpKey/finalKey for next round
    }

    if (tid == 0) {
        // softmax over (5 * selected sims); outv[0] is the max
        float m = outv[0] * 5.0f;
        float e[KNB], s = 0.0f;
        #pragma unroll
        for (int t = 0; t < KNB; t++) {
            e[t] = expf(outv[t] * 5.0f - m);
            s += e[t];
        }
        float inv = 1.0f / s;

        size_t base = ((size_t)b * NPTS + x) * KNB;
        float* vals = out;
        float* idxs = out + (size_t)BATCH * NPTS * KNB;
        #pragma unroll
        for (int t = 0; t < KNB; t++) {
            vals[base + t] = e[t] * inv;
            idxs[base + t] = (float)outi[t];
        }
    }
}

// ---------------------------------------------------------------------------
// Launch
// ---------------------------------------------------------------------------
extern "C" void kernel_launch(void* const* d_in, const int* in_sizes, int n_in,
                              void* d_out, int out_size)
{
    const float* feat_x = (const float*)d_in[0];
    const float* feat_y = (const float*)d_in[1];
    float* out = (float*)d_out;

    norm_kernel<<<2 * BATCH * NPTS, CDIM>>>(feat_x, feat_y);

    dim3 ggrid(NPTS / BN, NPTS / BM, BATCH);
    sgemm_nt_kernel<<<ggrid, 256>>>();

    dim3 tgrid(NPTS, BATCH);
    topk_kernel<<<tgrid, 256>>>(out);
}

// round 6
// speedup vs baseline: 1.1440x; 1.1440x over previous
#include <cuda_runtime.h>
#include <cuda_bf16.h>
#include <math.h>
#include <stdint.h>

// Problem constants
#define BATCH 2
#define NPTS  8192
#define CDIM  256
#define KNB   15
#define NCAND 32        // approximate-top-32 candidate shortlist (rescored exactly)
// tau = 0.2 -> scale winners by 5.0 before softmax (monotone => same selection)

// ---------------------------------------------------------------------------
// Static device scratch
// ---------------------------------------------------------------------------
__device__ float         g_fx [(size_t)BATCH * NPTS * CDIM];  // exact normalized
__device__ float         g_fy [(size_t)BATCH * NPTS * CDIM];
__device__ __nv_bfloat16 g_fxh[(size_t)BATCH * NPTS * CDIM];  // bf16 copies
__device__ __nv_bfloat16 g_fyh[(size_t)BATCH * NPTS * CDIM];
__device__ float         g_sim[(size_t)BATCH * NPTS * NPTS];  // approx sim (bf16 mma)

// ---------------------------------------------------------------------------
// Kernel 1: L2-normalize rows; emit fp32 (exact, true division) + bf16 copies.
// ---------------------------------------------------------------------------
__global__ __launch_bounds__(CDIM) void norm_kernel(const float* __restrict__ x,
                                                    const float* __restrict__ y)
{
    int row = blockIdx.x;
    const int total = BATCH * NPTS;
    const float* src;
    float* dst;  __nv_bfloat16* dsth;
    if (row < total) {
        src  = x + (size_t)row * CDIM;
        dst  = g_fx  + (size_t)row * CDIM;
        dsth = g_fxh + (size_t)row * CDIM;
    } else {
        row -= total;
        src  = y + (size_t)row * CDIM;
        dst  = g_fy  + (size_t)row * CDIM;
        dsth = g_fyh + (size_t)row * CDIM;
    }

    float v = src[threadIdx.x];
    float s = v * v;

    __shared__ float red[8];
    #pragma unroll
    for (int o = 16; o; o >>= 1) s += __shfl_xor_sync(0xffffffffu, s, o);
    if ((threadIdx.x & 31) == 0) red[threadIdx.x >> 5] = s;
    __syncthreads();
    if (threadIdx.x < 8) {
        float t = red[threadIdx.x];
        #pragma unroll
        for (int o = 4; o; o >>= 1) t += __shfl_xor_sync(0xffu, t, o);
        if (threadIdx.x == 0) red[0] = t;
    }
    __syncthreads();

    float norm = fmaxf(sqrtf(red[0]), 1e-12f);
    float nv = v / norm;                 // true division, matches reference
    dst[threadIdx.x]  = nv;
    dsth[threadIdx.x] = __float2bfloat16(nv);
}

// ---------------------------------------------------------------------------
// Kernel 2: bf16 tensor-core NT-GEMM via mma.sync.m16n8k16 (fp32 accum).
//   sim[b] = fxh[b] (8192x256) * fyh[b]^T. 128x128 block tile, 8 warps in a
//   2(m) x 4(n) grid, 64x32 warp tile. K-chunks of 32 with register-staged
//   prefetch. Smem rows padded to 40 bf16 -> fragment b32 loads hit 32
//   distinct banks. __launch_bounds__(256,2) for 2 CTAs/SM.
// ---------------------------------------------------------------------------
#define GKC 32

__device__ __forceinline__ void mma_bf16(float c[4],
    uint32_t a0, uint32_t a1, uint32_t a2, uint32_t a3,
    uint32_t b0, uint32_t b1)
{
    asm volatile(
        "mma.sync.aligned.m16n8k16.row.col.f32.bf16.bf16.f32 "
        "{%0,%1,%2,%3},{%4,%5,%6,%7},{%8,%9},{%0,%1,%2,%3};"
        : "+f"(c[0]), "+f"(c[1]), "+f"(c[2]), "+f"(c[3])
        : "r"(a0), "r"(a1), "r"(a2), "r"(a3), "r"(b0), "r"(b1));
}

__global__ __launch_bounds__(256, 2) void mma_gemm_kernel()
{
    const int b = blockIdx.z;
    const __nv_bfloat16* __restrict__ A  = g_fxh + (size_t)b * NPTS * CDIM;
    const __nv_bfloat16* __restrict__ Bm = g_fyh + (size_t)b * NPTS * CDIM;
    float* __restrict__ Cm = g_sim + (size_t)b * NPTS * NPTS;

    const int rowBase = blockIdx.y * 128;
    const int colBase = blockIdx.x * 128;

    __shared__ __nv_bfloat16 As[128][40];   // 10.25 KB (padded rows)
    __shared__ __nv_bfloat16 Bs[128][40];

    const int tid  = threadIdx.x;
    const int lane = tid & 31;
    const int wid  = tid >> 5;
    const int wm   = (wid >> 2) * 64;       // warp m-offset (0 or 64)
    const int wn   = (wid & 3) * 32;        // warp n-offset (0,32,64,96)
    const int gid  = lane >> 2;             // group id 0..7
    const int tig  = lane & 3;              // thread-in-group 0..3

    // gmem->smem mapping: thread owns 32 contiguous bytes of one row per chunk
    const int r  = tid & 127;
    const int uq = tid >> 7;                // 0 or 1

    const __nv_bfloat16* gra = A  + (size_t)(rowBase + r) * CDIM;
    const __nv_bfloat16* grb = Bm + (size_t)(colBase + r) * CDIM;

    float acc[2][4][4];
    #pragma unroll
    for (int mt = 0; mt < 2; mt++)
        #pragma unroll
        for (int nt = 0; nt < 4; nt++)
            #pragma unroll
            for (int i = 0; i < 4; i++) acc[mt][nt][i] = 0.0f;

    // Prefetch chunk 0
    uint4 sa0, sa1, sb0, sb1;
    {
        const uint4* qa = (const uint4*)(gra) + uq * 2;
        const uint4* qb = (const uint4*)(grb) + uq * 2;
        sa0 = qa[0]; sa1 = qa[1];
        sb0 = qb[0]; sb1 = qb[1];
    }

    // warp tile 64x32: mt in {0..3}? wm spans 64 rows -> 4 m16 tiles; we use
    // acc[2]... NOTE: 64 rows = 4 m-tiles. Use mt loop of 4 with acc[4][4][?]
    // -> rewritten below with 4 m-tiles and 2 n-tiles to keep 64 regs:
    // Actually: warp tile 64(m) x 32(n) = 4 m16-tiles x 4 n8-tiles = 64 regs.
    // acc[2][4][4] is insufficient; use acc4 layout:
    float acc4[4][4][4];
    #pragma unroll
    for (int mt = 0; mt < 4; mt++)
        #pragma unroll
        for (int nt = 0; nt < 4; nt++)
            #pragma unroll
            for (int i = 0; i < 4; i++) acc4[mt][nt][i] = 0.0f;

    for (int kc = 0; kc < CDIM / GKC; kc++) {
        // commit staged registers to smem
        *(uint4*)&As[r][uq * 16]     = sa0;
        *(uint4*)&As[r][uq * 16 + 8] = sa1;
        *(uint4*)&Bs[r][uq * 16]     = sb0;
        *(uint4*)&Bs[r][uq * 16 + 8] = sb1;
        __syncthreads();

        if (kc + 1 < CDIM / GKC) {
            const uint4* qa = (const uint4*)(gra + (kc + 1) * GKC) + uq * 2;
            const uint4* qb = (const uint4*)(grb + (kc + 1) * GKC) + uq * 2;
            sa0 = qa[0]; sa1 = qa[1];
            sb0 = qb[0]; sb1 = qb[1];
        }

        #pragma unroll
        for (int ks = 0; ks < 2; ks++) {            // two k16 steps per chunk
            const int kb = ks * 16 + tig * 2;
            uint32_t bfr[4][2];
            #pragma unroll
            for (int nt = 0; nt < 4; nt++) {
                const int nrow = wn + nt * 8 + gid;
                bfr[nt][0] = *(const uint32_t*)&Bs[nrow][kb];
                bfr[nt][1] = *(const uint32_t*)&Bs[nrow][kb + 8];
            }
            #pragma unroll
            for (int mt = 0; mt < 4; mt++) {
                const int mrow = wm + mt * 16 + gid;
                uint32_t a0 = *(const uint32_t*)&As[mrow][kb];
                uint32_t a1 = *(const uint32_t*)&As[mrow + 8][kb];
                uint32_t a2 = *(const uint32_t*)&As[mrow][kb + 8];
                uint32_t a3 = *(const uint32_t*)&As[mrow + 8][kb + 8];
                #pragma unroll
                for (int nt = 0; nt < 4; nt++)
                    mma_bf16(acc4[mt][nt], a0, a1, a2, a3, bfr[nt][0], bfr[nt][1]);
            }
        }
        __syncthreads();
    }

    // Epilogue: c0,c1 -> row g, cols t*2,t*2+1 ; c2,c3 -> row g+8
    #pragma unroll
    for (int mt = 0; mt < 4; mt++) {
        #pragma unroll
        for (int nt = 0; nt < 4; nt++) {
            int row0 = rowBase + wm + mt * 16 + gid;
            int col  = colBase + wn + nt * 8 + tig * 2;
            float2 lo = make_float2(acc4[mt][nt][0], acc4[mt][nt][1]);
            float2 hi = make_float2(acc4[mt][nt][2], acc4[mt][nt][3]);
            *(float2*)&Cm[(size_t)row0 * NPTS + col]       = lo;
            *(float2*)&Cm[(size_t)(row0 + 8) * NPTS + col] = hi;
        }
    }
}

// ---------------------------------------------------------------------------
// Kernel 3: per-row candidate selection (approx top-32) + EXACT fp32 rescore
//   + exact top-15 (val desc, idx asc) + softmax(x5). The bf16 GEMM noise
//   (<=4e-3 worst case) is far below the rank15->rank32 value gap (~0.02),
//   so the approx top-32 contains the true top-15; final ranking and output
//   values use exact fp32 dot products of the normalized features.
// ---------------------------------------------------------------------------
__device__ __forceinline__ bool tk_better(float v, int i, float v2, int i2)
{
    return v > v2 || (v == v2 && i < i2);
}

__device__ __forceinline__ void tk_insert(float v, int idx, float lv[KNB], int li[KNB])
{
    if (tk_better(v, idx, lv[KNB - 1], li[KNB - 1])) {
        lv[KNB - 1] = v; li[KNB - 1] = idx;
        #pragma unroll
        for (int k = KNB - 1; k > 0; k--) {
            if (tk_better(lv[k], li[k], lv[k - 1], li[k - 1])) {
                float tv = lv[k]; lv[k] = lv[k - 1]; lv[k - 1] = tv;
                int   ti = li[k]; li[k] = li[k - 1]; li[k - 1] = ti;
            }
        }
    }
}

__device__ __forceinline__ unsigned long long tk_key(float v, int idx, int tid)
{
    unsigned int u = __float_as_uint(v);
    unsigned int s = (u & 0x80000000u) ? ~u : (u | 0x80000000u); // monotone map
    unsigned int low = ((0x1FFFu & ~(unsigned int)idx) << 8) | (unsigned int)tid;
    return ((unsigned long long)s << 32) | low;
}

__global__ __launch_bounds__(256) void topk_kernel(float* __restrict__ out)
{
    const int x = blockIdx.x;
    const int b = blockIdx.y;
    const float4* __restrict__ row4 =
        (const float4*)(g_sim + ((size_t)b * NPTS + x) * NPTS);

    __shared__ float          sval[256 * KNB];
    __shared__ unsigned short sidx[256 * KNB];
    __shared__ unsigned long long warpKey[8];
    __shared__ unsigned long long finalKey;
    __shared__ int   cidx[NCAND];
    __shared__ float rsv[NCAND];
    __shared__ float fxrow[CDIM];

    const int tid  = threadIdx.x;
    const int lane = tid & 31;
    const int wid  = tid >> 5;

    // Phase 0: cache exact fx row
    if (tid < CDIM) fxrow[tid] = g_fx[((size_t)b * NPTS + x) * CDIM + tid];

    // Phase 1: per-thread top-15 over its 32 approx elements
    float lv[KNB]; int li[KNB];
    #pragma unroll
    for (int k = 0; k < KNB; k++) { lv[k] = -INFINITY; li[k] = 0x7fffffff; }

    #pragma unroll
    for (int j = 0; j < 8; j++) {
        float4 v = row4[tid + 256 * j];
        int base = 4 * (tid + 256 * j);
        tk_insert(v.x, base + 0, lv, li);
        tk_insert(v.y, base + 1, lv, li);
        tk_insert(v.z, base + 2, lv, li);
        tk_insert(v.w, base + 3, lv, li);
    }

    #pragma unroll
    for (int k = 0; k < KNB; k++) {
        sval[tid * KNB + k] = lv[k];
        sidx[tid * KNB + k] = (unsigned short)li[k];
    }
    __syncthreads();

    // Phase 2: extract approx top-32 (exact w.r.t. approx values)
    int p = 0;
    for (int t = 0; t < NCAND; t++) {
        unsigned long long key = 0ull;
        if (p < KNB) {
            float v  = sval[tid * KNB + p];
            int  idx = sidx[tid * KNB + p];
            key = tk_key(v, idx, tid);
        }
        #pragma unroll
        for (int o = 16; o; o >>= 1) {
            unsigned long long ok = __shfl_xor_sync(0xffffffffu, key, o);
            if (ok > key) key = ok;
        }
        if (lane == 0) warpKey[wid] = key;
        __syncthreads();

        if (tid < 8) {
            unsigned long long k2 = warpKey[tid];
            #pragma unroll
            for (int o = 4; o; o >>= 1) {
                unsigned long long ok = __shfl_xor_sync(0xffu, k2, o);
                if (ok > k2) k2 = ok;
            }
            if (tid == 0) finalKey = k2;
        }
        __syncthreads();

        unsigned long long fk = finalKey;
        if ((int)(fk & 0xffu) == tid) p++;          // winner advances its head
        if (tid == 0)
            cidx[t] = 0x1FFF - (int)((fk >> 8) & 0x1FFFu);
        __syncthreads();
    }

    // Phase 3: exact fp32 rescore of the 32 candidates (4 per warp)
    #pragma unroll
    for (int j = 0; j < 4; j++) {
        int c  = wid + 8 * j;
        int ci = cidx[c];
        const float* fy = g_fy + ((size_t)b * NPTS + ci) * CDIM;
        float s = 0.0f;
        #pragma unroll
        for (int k = 0; k < CDIM / 32; k++)
            s = fmaf(fxrow[lane + 32 * k], fy[lane + 32 * k], s);
        #pragma unroll
        for (int o = 16; o; o >>= 1) s += __shfl_xor_sync(0xffffffffu, s, o);
        if (lane == 0) rsv[c] = s;
    }
    __syncthreads();

    // Phase 4: warp 0 ranks the 32 exact values, softmax, writes output
    if (wid == 0) {
        float v  = rsv[lane];
        int  idx = cidx[lane];
        // key: [monotone-val(32) | ~idx(13)] ; unique since idx unique
        unsigned int u = __float_as_uint(v);
        unsigned int sgn = (u & 0x80000000u) ? ~u : (u | 0x80000000u);
        unsigned long long key =
            ((unsigned long long)sgn << 13) | (0x1FFFu & ~(unsigned int)idx);

        float outv[KNB]; int outi[KNB];
        #pragma unroll
        for (int t = 0; t < KNB; t++) {
            unsigned long long k2 = key;
            #pragma unroll
            for (int o = 16; o; o >>= 1) {
                unsigned long long ok = __shfl_xor_sync(0xffffffffu, k2, o);
                if (ok > k2) k2 = ok;
            }
            if (key == k2) key = 0ull;   // winner removes itself
            unsigned int ms = (unsigned int)(k2 >> 13);
            unsigned int uu = (ms & 0x80000000u) ? (ms & 0x7fffffffu) : ~ms;
            outv[t] = __uint_as_float(uu);
            outi[t] = 0x1FFF - (int)(k2 & 0x1FFFu);
        }

        if (lane == 0) {
            float m = outv[0] * 5.0f;
            float e[KNB], s = 0.0f;
            #pragma unroll
            for (int t = 0; t < KNB; t++) {
                e[t] = expf(outv[t] * 5.0f - m);
                s += e[t];
            }
            float inv = 1.0f / s;
            size_t base = ((size_t)b * NPTS + x) * KNB;
            float* vals = out;
            float* idxs = out + (size_t)BATCH * NPTS * KNB;
            #pragma unroll
            for (int t = 0; t < KNB; t++) {
                vals[base + t] = e[t] * inv;
                idxs[base + t] = (float)outi[t];
            }
        }
    }
}

// ---------------------------------------------------------------------------
// Launch
// ---------------------------------------------------------------------------
extern "C" void kernel_launch(void* const* d_in, const int* in_sizes, int n_in,
                              void* d_out, int out_size)
{
    const float* feat_x = (const float*)d_in[0];
    const float* feat_y = (const float*)d_in[1];
    float* out = (float*)d_out;

    norm_kernel<<<2 * BATCH * NPTS, CDIM>>>(feat_x, feat_y);

    dim3 ggrid(NPTS / 128, NPTS / 128, BATCH);
    mma_gemm_kernel<<<ggrid, 256>>>();

    dim3 tgrid(NPTS, BATCH);
    topk_kernel<<<tgrid, 256>>>(out);
}

// round 8
// speedup vs baseline: 1.9747x; 1.7260x over previous
#include <cuda_runtime.h>
#include <cuda_bf16.h>
#include <math.h>
#include <stdint.h>

// Problem constants
#define BATCH 2
#define NPTS  8192
#define CDIM  256
#define KNB   15
#define LCAP  20            // per-half-row candidate list depth (union 40/row)
#define NCAND 40
// tau = 0.2 -> scale winners by 5.0 (exact) before softmax.

// ---------------------------------------------------------------------------
// Static device scratch (no sim matrix anymore!)
// ---------------------------------------------------------------------------
__device__ float         g_fx [(size_t)BATCH * NPTS * CDIM];  // exact normalized
__device__ float         g_fy [(size_t)BATCH * NPTS * CDIM];
__device__ __nv_bfloat16 g_fxh[(size_t)BATCH * NPTS * CDIM];  // bf16 copies
__device__ __nv_bfloat16 g_fyh[(size_t)BATCH * NPTS * CDIM];
__device__ int           g_cand[(size_t)BATCH * NPTS * NCAND]; // 2.6 MB

// ---------------------------------------------------------------------------
// Kernel 1: L2-normalize rows; emit fp32 (true division) + bf16 copies.
// ---------------------------------------------------------------------------
__global__ __launch_bounds__(CDIM) void norm_kernel(const float* __restrict__ x,
                                                    const float* __restrict__ y)
{
    int row = blockIdx.x;
    const int total = BATCH * NPTS;
    const float* src;
    float* dst;  __nv_bfloat16* dsth;
    if (row < total) {
        src  = x + (size_t)row * CDIM;
        dst  = g_fx  + (size_t)row * CDIM;
        dsth = g_fxh + (size_t)row * CDIM;
    } else {
        row -= total;
        src  = y + (size_t)row * CDIM;
        dst  = g_fy  + (size_t)row * CDIM;
        dsth = g_fyh + (size_t)row * CDIM;
    }

    float v = src[threadIdx.x];
    float s = v * v;

    __shared__ float red[8];
    #pragma unroll
    for (int o = 16; o; o >>= 1) s += __shfl_xor_sync(0xffffffffu, s, o);
    if ((threadIdx.x & 31) == 0) red[threadIdx.x >> 5] = s;
    __syncthreads();
    if (threadIdx.x < 8) {
        float t = red[threadIdx.x];
        #pragma unroll
        for (int o = 4; o; o >>= 1) t += __shfl_xor_sync(0xffu, t, o);
        if (threadIdx.x == 0) red[0] = t;
    }
    __syncthreads();

    float norm = fmaxf(sqrtf(red[0]), 1e-12f);
    float nv = v / norm;                 // true division, matches reference
    dst[threadIdx.x]  = nv;
    dsth[threadIdx.x] = __float2bfloat16(nv);
}

// ---------------------------------------------------------------------------
// Kernel 2 (FUSED): bf16 mma GEMM strip + on-the-fly per-row candidate top-20
//   per column-half. One block owns 128 x-rows, sweeps all 8192 y cols in
//   64 tiles of 128. Sim values never reach DRAM.
//   mma mainloop layout identical to the round-6 verified kernel.
// ---------------------------------------------------------------------------
#define GKC 32
#define CT_STRIDE 129        // fp32 Ct row stride (odd -> low conflict reads)

// dynamic smem layout (bytes)
#define OFF_AS   0                       // [128][40] bf16 = 10240
#define OFF_BS   10240                   // [128][40] bf16 = 10240
#define OFF_CT   20480                   // [128][129] f32 = 66048
#define OFF_LV   86528                   // [256][20] f32  = 20480
#define OFF_LI   107008                  // [256][20] u16  = 10240
#define SMEM_FUSED 117248

__device__ __forceinline__ void mma_bf16(float c[4],
    uint32_t a0, uint32_t a1, uint32_t a2, uint32_t a3,
    uint32_t b0, uint32_t b1)
{
    asm volatile(
        "mma.sync.aligned.m16n8k16.row.col.f32.bf16.bf16.f32 "
        "{%0,%1,%2,%3},{%4,%5,%6,%7},{%8,%9},{%0,%1,%2,%3};"
        : "+f"(c[0]), "+f"(c[1]), "+f"(c[2]), "+f"(c[3])
        : "r"(a0), "r"(a1), "r"(a2), "r"(a3), "r"(b0), "r"(b1));
}

__device__ __forceinline__ bool tk_better(float v, int i, float v2, int i2)
{
    return v > v2 || (v == v2 && i < i2);
}

__global__ __launch_bounds__(256, 1) void fused_kernel()
{
    extern __shared__ char dsm[];
    __nv_bfloat16 (*As)[40] = (__nv_bfloat16(*)[40])(dsm + OFF_AS);
    __nv_bfloat16 (*Bs)[40] = (__nv_bfloat16(*)[40])(dsm + OFF_BS);
    float* Ct  = (float*)(dsm + OFF_CT);
    float* lvs = (float*)(dsm + OFF_LV);
    unsigned short* lis = (unsigned short*)(dsm + OFF_LI);

    const int b = blockIdx.y;
    const int rowBase = blockIdx.x * 128;
    const __nv_bfloat16* __restrict__ A  = g_fxh + (size_t)b * NPTS * CDIM;
    const __nv_bfloat16* __restrict__ Bm = g_fyh + (size_t)b * NPTS * CDIM;

    const int tid  = threadIdx.x;
    const int lane = tid & 31;
    const int wid  = tid >> 5;
    const int wm   = (wid >> 2) * 64;       // warp m-offset (0 or 64)
    const int wn   = (wid & 3) * 32;        // warp n-offset (0,32,64,96)
    const int gid  = lane >> 2;             // 0..7
    const int tig  = lane & 3;              // 0..3

    const int r  = tid & 127;               // load-mapping row
    const int uq = tid >> 7;                // 0 or 1
    const __nv_bfloat16* gra = A + (size_t)(rowBase + r) * CDIM;

    // selection identity: 2 threads per row, one column-half each
    const int srow  = tid >> 1;
    const int shalf = tid & 1;
    const int lbase = tid * LCAP;

    // init candidate lists (own slots only) + threshold regs
    #pragma unroll
    for (int j = 0; j < LCAP; j++) {
        lvs[lbase + j] = -INFINITY;
        lis[lbase + j] = 0xFFFFu;
    }
    float tv = -INFINITY; int ti = 0xFFFF;

    for (int yt = 0; yt < NPTS / 128; yt++) {
        const __nv_bfloat16* grb = Bm + (size_t)(yt * 128 + r) * CDIM;

        float acc4[4][4][4];
        #pragma unroll
        for (int mt = 0; mt < 4; mt++)
            #pragma unroll
            for (int nt = 0; nt < 4; nt++)
                #pragma unroll
                for (int i = 0; i < 4; i++) acc4[mt][nt][i] = 0.0f;

        // prefetch chunk 0
        uint4 sa0, sa1, sb0, sb1;
        {
            const uint4* qa = (const uint4*)(gra) + uq * 2;
            const uint4* qb = (const uint4*)(grb) + uq * 2;
            sa0 = qa[0]; sa1 = qa[1];
            sb0 = qb[0]; sb1 = qb[1];
        }

        for (int kc = 0; kc < CDIM / GKC; kc++) {
            *(uint4*)&As[r][uq * 16]     = sa0;
            *(uint4*)&As[r][uq * 16 + 8] = sa1;
            *(uint4*)&Bs[r][uq * 16]     = sb0;
            *(uint4*)&Bs[r][uq * 16 + 8] = sb1;
            __syncthreads();

            if (kc + 1 < CDIM / GKC) {
                const uint4* qa = (const uint4*)(gra + (kc + 1) * GKC) + uq * 2;
                const uint4* qb = (const uint4*)(grb + (kc + 1) * GKC) + uq * 2;
                sa0 = qa[0]; sa1 = qa[1];
                sb0 = qb[0]; sb1 = qb[1];
            }

            #pragma unroll
            for (int ks = 0; ks < 2; ks++) {
                const int kb = ks * 16 + tig * 2;
                uint32_t bfr[4][2];
                #pragma unroll
                for (int nt = 0; nt < 4; nt++) {
                    const int nrow = wn + nt * 8 + gid;
                    bfr[nt][0] = *(const uint32_t*)&Bs[nrow][kb];
                    bfr[nt][1] = *(const uint32_t*)&Bs[nrow][kb + 8];
                }
                #pragma unroll
                for (int mt = 0; mt < 4; mt++) {
                    const int mrow = wm + mt * 16 + gid;
                    uint32_t a0 = *(const uint32_t*)&As[mrow][kb];
                    uint32_t a1 = *(const uint32_t*)&As[mrow + 8][kb];
                    uint32_t a2 = *(const uint32_t*)&As[mrow][kb + 8];
                    uint32_t a3 = *(const uint32_t*)&As[mrow + 8][kb + 8];
                    #pragma unroll
                    for (int nt = 0; nt < 4; nt++)
                        mma_bf16(acc4[mt][nt], a0, a1, a2, a3,
                                 bfr[nt][0], bfr[nt][1]);
                }
            }
            __syncthreads();
        }

        // stage acc -> Ct (scalar stores, low-conflict odd stride)
        #pragma unroll
        for (int mt = 0; mt < 4; mt++) {
            #pragma unroll
            for (int nt = 0; nt < 4; nt++) {
                int row0 = wm + mt * 16 + gid;
                int col  = wn + nt * 8 + tig * 2;
                Ct[row0 * CT_STRIDE + col]           = acc4[mt][nt][0];
                Ct[row0 * CT_STRIDE + col + 1]       = acc4[mt][nt][1];
                Ct[(row0 + 8) * CT_STRIDE + col]     = acc4[mt][nt][2];
                Ct[(row0 + 8) * CT_STRIDE + col + 1] = acc4[mt][nt][3];
            }
        }
        __syncthreads();

        // selection: this thread scans 64 values of its (row, half)
        const float* __restrict__ crow = Ct + srow * CT_STRIDE + shalf * 64;
        const int cbase = yt * 128 + shalf * 64;
        #pragma unroll 4
        for (int i = 0; i < 64; i++) {
            float v = crow[i];
            int idx = cbase + i;
            if (v > tv || (v == tv && idx < ti)) {
                // bubble-insert into sorted (desc, idx-asc) smem list
                int j = LCAP - 1;
                while (j > 0 && tk_better(v, idx, lvs[lbase + j - 1],
                                          (int)lis[lbase + j - 1])) {
                    lvs[lbase + j] = lvs[lbase + j - 1];
                    lis[lbase + j] = lis[lbase + j - 1];
                    j--;
                }
                lvs[lbase + j] = v;
                lis[lbase + j] = (unsigned short)idx;
                tv = lvs[lbase + LCAP - 1];
                ti = (int)lis[lbase + LCAP - 1];
            }
        }
        // no sync needed: next Ct write happens after next K-loop's barriers
    }

    // emit candidate indices
    int* __restrict__ cp =
        g_cand + ((size_t)b * NPTS + rowBase + srow) * NCAND + shalf * LCAP;
    #pragma unroll
    for (int j = 0; j < LCAP; j++)
        cp[j] = (int)lis[lbase + j];
}

// ---------------------------------------------------------------------------
// Kernel 3: exact fp32 rescore of 40 candidates/row + exact top-15 ranking
//   (val desc, idx asc) + softmax(x5). Same op order as the round-6 verified
//   rescore path.
// ---------------------------------------------------------------------------
__device__ __forceinline__ unsigned long long rk_key(float v, int idx)
{
    unsigned int u = __float_as_uint(v);
    unsigned int s = (u & 0x80000000u) ? ~u : (u | 0x80000000u);
    return ((unsigned long long)s << 13) | (0x1FFFu & ~(unsigned int)idx);
}

__global__ __launch_bounds__(256) void rescore_kernel(float* __restrict__ out)
{
    const int x = blockIdx.x;
    const int b = blockIdx.y;

    __shared__ float fxrow[CDIM];
    __shared__ int   scand[NCAND];
    __shared__ float rsv[NCAND];

    const int tid  = threadIdx.x;
    const int lane = tid & 31;
    const int wid  = tid >> 5;

    fxrow[tid] = g_fx[((size_t)b * NPTS + x) * CDIM + tid];
    if (tid < NCAND)
        scand[tid] = g_cand[((size_t)b * NPTS + x) * NCAND + tid];
    __syncthreads();

    // 8 warps x 5 candidates
    #pragma unroll
    for (int j = 0; j < 5; j++) {
        int c  = wid + 8 * j;
        int ci = scand[c];
        const float* fy = g_fy + ((size_t)b * NPTS + ci) * CDIM;
        float s = 0.0f;
        #pragma unroll
        for (int k = 0; k < CDIM / 32; k++)
            s = fmaf(fxrow[lane + 32 * k], fy[lane + 32 * k], s);
        #pragma unroll
        for (int o = 16; o; o >>= 1) s += __shfl_xor_sync(0xffffffffu, s, o);
        if (lane == 0) rsv[c] = s;
    }
    __syncthreads();

    if (wid == 0) {
        unsigned long long k0 = rk_key(rsv[lane], scand[lane]);
        unsigned long long k1 = (lane < 8)
            ? rk_key(rsv[32 + lane], scand[32 + lane]) : 0ull;

        float outv[KNB]; int outi[KNB];
        #pragma unroll
        for (int t = 0; t < KNB; t++) {
            unsigned long long cur = k0 > k1 ? k0 : k1;
            unsigned long long m = cur;
            #pragma unroll
            for (int o = 16; o; o >>= 1) {
                unsigned long long om = __shfl_xor_sync(0xffffffffu, m, o);
                if (om > m) m = om;
            }
            if (k0 == m) k0 = 0ull;
            else if (k1 == m) k1 = 0ull;
            unsigned int s = (unsigned int)(m >> 13);
            unsigned int u = (s & 0x80000000u) ? (s & 0x7fffffffu) : ~s;
            outv[t] = __uint_as_float(u);
            outi[t] = 0x1FFF - (int)(m & 0x1FFFu);
        }

        if (lane == 0) {
            float mx = outv[0] * 5.0f;
            float e[KNB], s = 0.0f;
            #pragma unroll
            for (int t = 0; t < KNB; t++) {
                e[t] = expf(outv[t] * 5.0f - mx);
                s += e[t];
            }
            float inv = 1.0f / s;
            size_t base = ((size_t)b * NPTS + x) * KNB;
            float* vals = out;
            float* idxs = out + (size_t)BATCH * NPTS * KNB;
            #pragma unroll
            for (int t = 0; t < KNB; t++) {
                vals[base + t] = e[t] * inv;
                idxs[base + t] = (float)outi[t];
            }
        }
    }
}

// ---------------------------------------------------------------------------
// Launch
// ---------------------------------------------------------------------------
extern "C" void kernel_launch(void* const* d_in, const int* in_sizes, int n_in,
                              void* d_out, int out_size)
{
    const float* feat_x = (const float*)d_in[0];
    const float* feat_y = (const float*)d_in[1];
    float* out = (float*)d_out;

    // idempotent; first (uncaptured) call establishes the attribute
    cudaFuncSetAttribute(fused_kernel,
                         cudaFuncAttributeMaxDynamicSharedMemorySize,
                         SMEM_FUSED);

    norm_kernel<<<2 * BATCH * NPTS, CDIM>>>(feat_x, feat_y);

    dim3 fgrid(NPTS / 128, BATCH);
    fused_kernel<<<fgrid, 256, SMEM_FUSED>>>();

    dim3 rgrid(NPTS, BATCH);
    rescore_kernel<<<rgrid, 256>>>(out);
}